// round 15
// baseline (speedup 1.0000x reference)
#include <cuda_runtime.h>

#define Bz 4
#define Nz 8192
#define Mz 2048
#define Kz 20
#define Cz 64
#define PTS (Bz*Mz*Kz)   // 163840
#define NSLICE 8
#define SLEN 1024
#define NWORK 144
#define FUSED_SMEM (3*Nz*4)   // 96kB dynamic

typedef unsigned long long ull;

// ---------------- packed f32x2 helpers (sm_100+: add/mul/fma only) ----------------
__device__ __forceinline__ ull PK(float lo, float hi) {
    ull r; asm("mov.b64 %0, {%1,%2};" : "=l"(r) : "f"(lo), "f"(hi)); return r;
}
__device__ __forceinline__ void UPK(ull v, float& lo, float& hi) {
    asm("mov.b64 {%0,%1}, %2;" : "=f"(lo), "=f"(hi) : "l"(v));
}
__device__ __forceinline__ ull ADD2(ull a, ull b) {
    ull r; asm("add.rn.f32x2 %0, %1, %2;" : "=l"(r) : "l"(a), "l"(b)); return r;
}
__device__ __forceinline__ ull MUL2(ull a, ull b) {
    ull r; asm("mul.rn.f32x2 %0, %1, %2;" : "=l"(r) : "l"(a), "l"(b)); return r;
}
__device__ __forceinline__ ull FMA2(ull a, ull b, ull c) {
    ull r; asm("fma.rn.f32x2 %0, %1, %2, %3;" : "=l"(r) : "l"(a), "l"(b), "l"(c)); return r;
}

// ---------------- scratch (static device globals; no allocation) ----------------
__device__ float4 g_q[Bz*Mz];                    // sampled pts: x,y,z,|q|^2
__device__ int    g_nidx[Bz*Mz*Kz];              // final knn indices
__device__ float  g_kd[Bz*Mz*NSLICE*Kz];         // per-slice partial top-20 dists
__device__ int    g_ki[Bz*Mz*NSLICE*Kz];         // per-slice partial top-20 idx
__device__ float  g_x1[(size_t)PTS*Cz];          // ~42MB
__device__ float  g_x2[(size_t)PTS*Cz];          // ~42MB
__device__ double g_sum[2*Cz];                   // per-channel sum/sumsq (re-zeroed by bnfin)
__device__ float  g_aff[3*2*Cz];                 // per-stage BN affine: a[64], c[64]
__device__ volatile unsigned g_prog[Bz];         // FPS progress per batch (handshake)
__device__ ull    g_wpack[2][2048];              // packed conv2/conv3 weights: [cg][j][qq]

extern __shared__ float fused_sm[];

// ===== FPS role (round-10 measured-best: tree max, REDUX, two barriers, atomicMin) ===========
__device__ void fps_body(const float* __restrict__ p, int b) {
    const int tid = threadIdx.x;
    const float* pb = p + (size_t)b*Nz*3;
    float* spx = fused_sm; float* spy = fused_sm + Nz; float* spz = fused_sm + 2*Nz;
    __shared__ unsigned s_bv[8];
    __shared__ unsigned s_wi[2];

    for (int i = tid; i < Nz; i += 256) {
        spx[i] = pb[3*i+0]; spy[i] = pb[3*i+1]; spz[i] = pb[3*i+2];
    }
    if (tid == 0) { s_wi[0] = 0xFFFFFFFFu; s_wi[1] = 0xFFFFFFFFu; }
    __syncthreads();

    ull px2[16], py2[16], pz2[16];
    float dd[32];
#pragma unroll
    for (int u = 0; u < 16; ++u) {
        int i0 = tid + (2*u)*256, i1 = i0 + 256;
        px2[u] = PK(spx[i0], spx[i1]);
        py2[u] = PK(spy[i0], spy[i1]);
        pz2[u] = PK(spz[i0], spz[i1]);
        dd[2*u] = 1e10f; dd[2*u+1] = 1e10f;
    }
    float lx = spx[0], ly = spy[0], lz = spz[0];
    if (tid == 0) {
        float qq = __fadd_rn(__fadd_rn(__fmul_rn(lx,lx), __fmul_rn(ly,ly)), __fmul_rn(lz,lz));
        g_q[b*Mz] = make_float4(lx, ly, lz, qq);
    }

    for (int t = 1; t < Mz; ++t) {
        const ull nx2 = PK(-lx,-lx), ny2 = PK(-ly,-ly), nz2 = PK(-lz,-lz);
        float m[16];
#pragma unroll
        for (int u = 0; u < 16; ++u) {
            ull dx2 = ADD2(px2[u], nx2);
            ull dy2 = ADD2(py2[u], ny2);
            ull dz2 = ADD2(pz2[u], nz2);
            ull d2  = MUL2(dx2, dx2);
            d2 = FMA2(dy2, dy2, d2);
            d2 = FMA2(dz2, dz2, d2);
            float d0, d1; UPK(d2, d0, d1);
            float n0 = fminf(dd[2*u],   d0);
            float n1 = fminf(dd[2*u+1], d1);
            dd[2*u] = n0; dd[2*u+1] = n1;
            m[u] = fmaxf(n0, n1);
        }
#pragma unroll
        for (int s = 8; s; s >>= 1)
#pragma unroll
            for (int i = 0; i < s; ++i) m[i] = fmaxf(m[i], m[i+s]);
        const float bv = m[0];
        unsigned wmax = __reduce_max_sync(0xffffffffu, __float_as_uint(bv));
        if ((tid & 31) == 0) s_bv[tid >> 5] = wmax;
        __syncthreads();                               // bar 1
        unsigned gb = s_bv[0];
#pragma unroll
        for (int w = 1; w < 8; ++w) gb = umax(gb, s_bv[w]);
        const float bvg = __uint_as_float(gb);
        const int buf = t & 1;
        if (tid == 0) s_wi[buf^1] = 0xFFFFFFFFu;
        if (__float_as_uint(bv) == gb) {
            unsigned best = 0xFFFFFFFFu;
#pragma unroll
            for (int u = 31; u >= 0; --u)
                if (dd[u] == bvg) best = (unsigned)(tid + u*256);
            atomicMin(&s_wi[buf], best);               // lowest global index wins ties
        }
        __syncthreads();                               // bar 2
        const unsigned wi = s_wi[buf];
        lx = spx[wi]; ly = spy[wi]; lz = spz[wi];
        if (tid == 0) {
            float qq = __fadd_rn(__fadd_rn(__fmul_rn(lx,lx), __fmul_rn(ly,ly)), __fmul_rn(lz,lz));
            g_q[b*Mz + t] = make_float4(lx, ly, lz, qq);
            if ((t & 63) == 63) {
                __threadfence();
                g_prog[b] = (unsigned)(t + 1);
            }
        }
    }
}

// ===== kNN slice unit: waits on FPS progress (producer resident: single wave) ================
__device__ void knn_unit(const float* __restrict__ p, int e) {
    ull (*spt)[4] = (ull(*)[4])fused_sm;    // 16kB tile
    const int tid = threadIdx.x;
    const int qb = e & 31, sl = e >> 5;
    const int b  = qb >> 3;
    const float* pb = p + (size_t)b*Nz*3;
    const int t0 = sl * SLEN;

    for (int i = tid; i < SLEN/2; i += 256) {
        int i0 = t0 + 2*i, i1 = i0 + 1;
        float x0 = pb[3*i0+0], y0 = pb[3*i0+1], z0 = pb[3*i0+2];
        float x1 = pb[3*i1+0], y1 = pb[3*i1+1], z1 = pb[3*i1+2];
        float w0 = __fadd_rn(__fadd_rn(__fmul_rn(x0,x0), __fmul_rn(y0,y0)), __fmul_rn(z0,z0));
        float w1 = __fadd_rn(__fadd_rn(__fmul_rn(x1,x1), __fmul_rn(y1,y1)), __fmul_rn(z1,z1));
        spt[i][0] = PK(x0,x1); spt[i][1] = PK(y0,y1);
        spt[i][2] = PK(z0,z1); spt[i][3] = PK(w0,w1);
    }
    if (tid == 0) {
        const unsigned need = ((unsigned)(qb & 7) + 1u) * 256u;
        while (g_prog[b] < need) __nanosleep(256);
        __threadfence();
    }
    __syncthreads();

    const int qi = qb*256 + tid;
    const float4 q = g_q[qi];
    const ull qx2 = PK(q.x,q.x), qy2 = PK(q.y,q.y), qz2 = PK(q.z,q.z);
    const ull qw2 = PK(q.w,q.w), n2 = PK(-2.0f,-2.0f);

    float nd[Kz]; int ni[Kz];
#pragma unroll
    for (int j = 0; j < Kz; ++j) { nd[j] = 1e30f; ni[j] = 0; }
    float wk = 1e30f;

    for (int u = 0; u < SLEN/2; ++u) {
        const ulonglong2* r = (const ulonglong2*)spt[u];
        ulonglong2 r0 = r[0], r1 = r[1];
        ull a2 = MUL2(qx2, r0.x);
        a2 = FMA2(qy2, r0.y, a2);
        a2 = FMA2(qz2, r1.x, a2);
        ull a3 = ADD2(qw2, r1.y);
        ull d2 = FMA2(a2, n2, a3);
        float d0, d1; UPK(d2, d0, d1);
        if (d0 < wk) {
            float cd = d0; int ci = t0 + 2*u;
#pragma unroll
            for (int j = 0; j < Kz; ++j)
                if (cd < nd[j]) { float td = nd[j]; int ti = ni[j]; nd[j] = cd; ni[j] = ci; cd = td; ci = ti; }
            wk = nd[Kz-1];
        }
        if (d1 < wk) {
            float cd = d1; int ci = t0 + 2*u + 1;
#pragma unroll
            for (int j = 0; j < Kz; ++j)
                if (cd < nd[j]) { float td = nd[j]; int ti = ni[j]; nd[j] = cd; ni[j] = ci; cd = td; ci = ti; }
            wk = nd[Kz-1];
        }
    }
    const size_t base = ((size_t)qi*NSLICE + sl)*Kz;
#pragma unroll
    for (int j = 0; j < Kz; ++j) { g_kd[base+j] = nd[j]; g_ki[base+j] = ni[j]; }
}

// ===== fused kernel: 148 blocks = one wave; FPS || kNN ======================================
__global__ void __launch_bounds__(256,1) fused_kernel(const float* __restrict__ p) {
    if (blockIdx.x < Bz) {
        fps_body(p, blockIdx.x);
        return;
    }
    const int w = blockIdx.x - Bz;           // 0..143
    knn_unit(p, w);
    if (w + NWORK < 256) {
        __syncthreads();                     // protect smem tile reuse
        knn_unit(p, w + NWORK);
    }
}

// ---- weight prepack: g_wpack[s][cg*512 + j*8 + qq] = (W[c0][j], W[c0+1][j]), c0=cg*16+2qq ----
__global__ void wpack_kernel(const float* __restrict__ W2, const float* __restrict__ W3) {
    const int k = blockIdx.x*256 + threadIdx.x;      // [0, 2048)
    const int cg = k >> 9, rem = k & 511, j = rem >> 3, qq = rem & 7;
    const int c0 = cg*16 + 2*qq;
    g_wpack[0][k] = PK(W2[c0*64 + j], W2[(c0+1)*64 + j]);
    g_wpack[1][k] = PK(W3[c0*64 + j], W3[(c0+1)*64 + j]);
}

// ---- exact 8-way merge of per-slice sorted (d, idx) lists -> global top-20 ----
__global__ void __launch_bounds__(64) kmerge_kernel() {
    const int qi = blockIdx.x*64 + threadIdx.x;
    float dc[NSLICE]; int ic[NSLICE]; int h[NSLICE];
#pragma unroll
    for (int s = 0; s < NSLICE; ++s) {
        size_t base = ((size_t)qi*NSLICE + s)*Kz;
        dc[s] = g_kd[base]; ic[s] = g_ki[base]; h[s] = 0;
    }
    for (int j = 0; j < Kz; ++j) {
        int bs = 0;
#pragma unroll
        for (int s = 1; s < NSLICE; ++s)
            if (dc[s] < dc[bs] || (dc[s] == dc[bs] && ic[s] < ic[bs])) bs = s;
        g_nidx[(size_t)qi*Kz + j] = ic[bs];
        h[bs]++;
        if (h[bs] < Kz) {
            size_t off = ((size_t)qi*NSLICE + bs)*Kz + h[bs];
            dc[bs] = g_kd[off]; ic[bs] = g_ki[off];
        } else { dc[bs] = 3.0e38f; ic[bs] = 0x7FFFFFFF; }
    }
}

// ====== conv1: half-tiles (64 pts x 2 ch-halves), 2 iters/block, high occupancy ======
__global__ void __launch_bounds__(128) conv1_kernel(const float* __restrict__ p,
                                                    const float* __restrict__ W1) {
    __shared__ __align__(16) float sWc[64][8];
    __shared__ __align__(16) float so[64*68];        // 17.4kB half-tile
    __shared__ __align__(16) float sf[64][8];        // point features (6 used)
    __shared__ float sps[2][64], sqs[2][64];
    const int tid = threadIdx.x;
    if (tid < 64) {
#pragma unroll
        for (int j = 0; j < 6; ++j) sWc[tid][j] = W1[tid*6 + j];
        sWc[tid][6] = 0.f; sWc[tid][7] = 0.f;
    }
    const int pt = tid & 63, half = tid >> 6;        // 64 pts x 2 channel halves
    float accS = 0.f, accQ = 0.f;                    // per-thread running stats partials

#pragma unroll 1
    for (int tile = 0; tile < 2; ++tile) {
        const int gp0 = blockIdx.x*128 + tile*64;
        if (tid < 64) {                              // gather (one thread per point)
            int gp = gp0 + tid;
            int m = (gp / Kz) % Mz;
            int b = gp / (Kz*Mz);
            int nid = g_nidx[gp];
            const float* pr = p + ((size_t)b*Nz + nid)*3;
            float gx = pr[0], gy = pr[1], gz = pr[2];
            float4 q = g_q[b*Mz + m];
            sf[tid][0] = __fsub_rn(gx, q.x);
            sf[tid][1] = __fsub_rn(gy, q.y);
            sf[tid][2] = __fsub_rn(gz, q.z);
            sf[tid][3] = gx; sf[tid][4] = gy; sf[tid][5] = gz;
        }
        __syncthreads();
        float f0 = sf[pt][0], f1 = sf[pt][1], f2 = sf[pt][2];
        float gx = sf[pt][3], gy = sf[pt][4], gz = sf[pt][5];
        const int cbase = half*32;
#pragma unroll 4
        for (int ci = 0; ci < 32; ++ci) {
            int c = cbase + ci;
            float4 w0 = *(const float4*)&sWc[c][0];
            float2 w1 = *(const float2*)&sWc[c][4];
            float acc = w0.x * f0;
            acc = fmaf(w0.y, f1, acc);
            acc = fmaf(w0.z, f2, acc);
            acc = fmaf(w0.w, gx, acc);
            acc = fmaf(w1.x, gy, acc);
            acc = fmaf(w1.y, gz, acc);
            so[pt*68 + c] = (acc >= 0.f) ? acc : 0.2f*acc;
        }
        __syncthreads();
        {   // stats partials: channel c = tid&63, rows split by half
            int c = tid & 63;
            float s = 0.f, s2 = 0.f;
#pragma unroll 8
            for (int r = half*32; r < half*32 + 32; ++r) {
                float v = so[r*68 + c];
                s += v; s2 = fmaf(v, v, s2);
            }
            accS += s; accQ += s2;
        }
        // coalesced writeout: 64 rows x 16 float4 = 1024 / 128 thr = 8 each
        for (int idx = tid; idx < 1024; idx += 128) {
            int row = idx >> 4, sg = idx & 15;
            float4 v = *(const float4*)&so[row*68 + sg*4];
            *(float4*)(g_x1 + (size_t)(gp0 + row)*64 + sg*4) = v;
        }
        __syncthreads();   // so/sf reuse next tile
    }
    // combine the two half partials per channel and atomically accumulate
    sps[half][tid & 63] = accS; sqs[half][tid & 63] = accQ;
    __syncthreads();
    if (tid < 64) {
        atomicAdd(&g_sum[tid],      (double)(sps[0][tid] + sps[1][tid]));
        atomicAdd(&g_sum[64 + tid], (double)(sqs[0][tid] + sqs[1][tid]));
    }
}

// ======== conv2/3: FFMA2 [64->64] matvec, 4 pts/thread, weights via __ldg (L1 broadcast) ======
__global__ void __launch_bounds__(128,5) conv_kernel(int in_sel, int wsel, int aff_stage) {
    const float* xin = in_sel ? g_x2 : g_x1;
    float*      xout = in_sel ? g_x1 : g_x2;
    const ull* wp = g_wpack[wsel];
    __shared__ __align__(16) float sx[128][65];
    __shared__ float sa[64], sc[64];
    __shared__ float ssumW[4*64], ssqW[4*64];
    const int tid = threadIdx.x;
    const int ww = tid >> 5, lane = tid & 31;

    if (tid < 64) {
        sa[tid] = g_aff[aff_stage*128 + tid];
        sc[tid] = g_aff[aff_stage*128 + 64 + tid];
    }
    __syncthreads();
    const int p0 = blockIdx.x * 128;
    for (int idx = tid; idx < 8192; idx += 128) {
        int j = idx & 63;
        float v = xin[(size_t)p0*64 + idx];
        sx[idx >> 6][j] = fmaf(sa[j], v, sc[j]);
    }
    __syncthreads();

    const int ptb = tid >> 2, cg = tid & 3;
    const ull* wbase = wp + cg*512;
    ull acc[4][8];
#pragma unroll
    for (int k = 0; k < 4; ++k)
#pragma unroll
        for (int qq = 0; qq < 8; ++qq) acc[k][qq] = 0ull;

    for (int j = 0; j < 64; ++j) {
        const ulonglong2* wr = (const ulonglong2*)(wbase + j*8);
        ulonglong2 w01 = __ldg(wr + 0), w23 = __ldg(wr + 1);
        ulonglong2 w45 = __ldg(wr + 2), w67 = __ldg(wr + 3);
        ull wv[8] = {w01.x, w01.y, w23.x, w23.y, w45.x, w45.y, w67.x, w67.y};
#pragma unroll
        for (int k = 0; k < 4; ++k) {
            float xv = sx[ptb + 32*k][j];
            ull xv2 = PK(xv, xv);
#pragma unroll
            for (int qq = 0; qq < 8; ++qq)
                acc[k][qq] = FMA2(wv[qq], xv2, acc[k][qq]);
        }
    }
    float sacc[16], sqacc[16];
#pragma unroll
    for (int i = 0; i < 16; ++i) { sacc[i] = 0.f; sqacc[i] = 0.f; }
#pragma unroll
    for (int k = 0; k < 4; ++k) {
        float o[16];
#pragma unroll
        for (int qq = 0; qq < 8; ++qq) {
            float lo, hi; UPK(acc[k][qq], lo, hi);
            o[2*qq]   = (lo >= 0.f) ? lo : 0.2f*lo;
            o[2*qq+1] = (hi >= 0.f) ? hi : 0.2f*hi;
        }
#pragma unroll
        for (int i = 0; i < 16; ++i) {
            sacc[i] += o[i];
            sqacc[i] = fmaf(o[i], o[i], sqacc[i]);
        }
        float4* op = (float4*)(xout + (size_t)(p0 + ptb + 32*k)*64 + cg*16);
#pragma unroll
        for (int v4 = 0; v4 < 4; ++v4)
            op[v4] = make_float4(o[4*v4], o[4*v4+1], o[4*v4+2], o[4*v4+3]);
    }
    // reduce over the 8 same-cg lanes in this warp (xor 4,8,16)
#pragma unroll
    for (int o = 4; o <= 16; o <<= 1) {
#pragma unroll
        for (int i = 0; i < 16; ++i) {
            sacc[i]  += __shfl_xor_sync(0xffffffffu, sacc[i],  o);
            sqacc[i] += __shfl_xor_sync(0xffffffffu, sqacc[i], o);
        }
    }
    if (lane < 4) {
#pragma unroll
        for (int i = 0; i < 16; ++i) {
            ssumW[ww*64 + lane*16 + i] = sacc[i];
            ssqW [ww*64 + lane*16 + i] = sqacc[i];
        }
    }
    __syncthreads();
    if (tid < 64) {
        float S = 0.f, Q = 0.f;
#pragma unroll
        for (int v = 0; v < 4; ++v) { S += ssumW[v*64 + tid]; Q += ssqW[v*64 + tid]; }
        atomicAdd(&g_sum[tid],      (double)S);
        atomicAdd(&g_sum[64 + tid], (double)Q);
    }
}

// ---------------- BN finalize: affine a,c; re-zeroes accumulators ----------------
__global__ void bnfin_kernel(int stage, const float* __restrict__ g, const float* __restrict__ bb) {
    const int c = threadIdx.x;   // 64 threads
    const double cnt = (double)PTS;
    double mean = g_sum[c] / cnt;
    double var  = g_sum[64 + c] / cnt - mean*mean;
    double inv  = 1.0 / sqrt(var + 1e-5);
    float a  = (float)((double)g[c] * inv);
    float cc = (float)((double)bb[c] - (double)a * mean);
    g_aff[stage*128 + c]      = a;
    g_aff[stage*128 + 64 + c] = cc;
    g_sum[c] = 0.0; g_sum[64 + c] = 0.0;
}

// ---------------- final: apply BN3 affine, max over K ----------------
__global__ void __launch_bounds__(256) maxk_kernel(float* __restrict__ out) {
    const int t = blockIdx.x*256 + threadIdx.x;
    const int c = t & 63;
    const int m = (t >> 6) & 2047;
    const int b = t >> 17;
    const float* base = g_x1 + ((size_t)(b*Mz + m)*Kz)*64 + c;
    const float a  = g_aff[2*128 + c];
    const float cc = g_aff[2*128 + 64 + c];
    float mx = -1e30f;
#pragma unroll
    for (int k = 0; k < Kz; ++k) {
        float v = fmaf(a, base[(size_t)k*64], cc);
        mx = fmaxf(mx, v);
    }
    out[((size_t)(b*64 + c))*Mz + m] = mx;
}

// ---------------- launch ----------------
extern "C" void kernel_launch(void* const* d_in, const int* in_sizes, int n_in,
                              void* d_out, int out_size) {
    (void)in_sizes; (void)n_in; (void)out_size;
    const float* p  = (const float*)d_in[0];
    const float* W1 = (const float*)d_in[1];
    const float* g1 = (const float*)d_in[2];
    const float* b1 = (const float*)d_in[3];
    const float* W2 = (const float*)d_in[4];
    const float* g2 = (const float*)d_in[5];
    const float* b2 = (const float*)d_in[6];
    const float* W3 = (const float*)d_in[7];
    const float* g3 = (const float*)d_in[8];
    const float* b3 = (const float*)d_in[9];
    float* out = (float*)d_out;

    cudaFuncSetAttribute(fused_kernel, cudaFuncAttributeMaxDynamicSharedMemorySize, FUSED_SMEM);

    wpack_kernel<<<8, 256>>>(W2, W3);
    fused_kernel<<<Bz + NWORK, 256, FUSED_SMEM>>>(p);
    kmerge_kernel<<<(Bz*Mz)/64, 64>>>();
    conv1_kernel<<<PTS/128, 128>>>(p, W1);
    bnfin_kernel<<<1, 64>>>(0, g1, b1);
    conv_kernel<<<PTS/128, 128>>>(0, 0, 0);
    bnfin_kernel<<<1, 64>>>(1, g2, b2);
    conv_kernel<<<PTS/128, 128>>>(1, 1, 1);
    bnfin_kernel<<<1, 64>>>(2, g3, b3);
    maxk_kernel<<<(Bz*Mz*Cz)/256, 256>>>(out);
}

// round 16
// speedup vs baseline: 1.1488x; 1.1488x over previous
#include <cuda_runtime.h>

#define Bz 4
#define Nz 8192
#define Mz 2048
#define Kz 20
#define Cz 64
#define PTS (Bz*Mz*Kz)   // 163840
#define NSLICE 8
#define SLEN 1024
#define NWORK 144
#define FUSED_SMEM (3*Nz*4)   // 96kB dynamic

typedef unsigned long long ull;

// ---------------- packed f32x2 helpers (sm_100+: add/mul/fma only) ----------------
__device__ __forceinline__ ull PK(float lo, float hi) {
    ull r; asm("mov.b64 %0, {%1,%2};" : "=l"(r) : "f"(lo), "f"(hi)); return r;
}
__device__ __forceinline__ void UPK(ull v, float& lo, float& hi) {
    asm("mov.b64 {%0,%1}, %2;" : "=f"(lo), "=f"(hi) : "l"(v));
}
__device__ __forceinline__ ull ADD2(ull a, ull b) {
    ull r; asm("add.rn.f32x2 %0, %1, %2;" : "=l"(r) : "l"(a), "l"(b)); return r;
}
__device__ __forceinline__ ull MUL2(ull a, ull b) {
    ull r; asm("mul.rn.f32x2 %0, %1, %2;" : "=l"(r) : "l"(a), "l"(b)); return r;
}
__device__ __forceinline__ ull FMA2(ull a, ull b, ull c) {
    ull r; asm("fma.rn.f32x2 %0, %1, %2, %3;" : "=l"(r) : "l"(a), "l"(b), "l"(c)); return r;
}

// ---------------- scratch (static device globals; no allocation) ----------------
__device__ float4 g_q[Bz*Mz];                    // sampled pts: x,y,z,|q|^2
__device__ int    g_nidx[Bz*Mz*Kz];              // final knn indices
__device__ float  g_kd[Bz*Mz*NSLICE*Kz];         // per-slice partial top-20 dists
__device__ int    g_ki[Bz*Mz*NSLICE*Kz];         // per-slice partial top-20 idx
__device__ float  g_x1[(size_t)PTS*Cz];          // ~42MB
__device__ float  g_x2[(size_t)PTS*Cz];          // ~42MB
__device__ double g_sum[2*Cz];                   // per-channel sum/sumsq (re-zeroed by bnfin)
__device__ float  g_aff[3*2*Cz];                 // per-stage BN affine: a[64], c[64]
__device__ volatile unsigned g_prog[Bz];         // FPS progress per batch (handshake)

extern __shared__ float fused_sm[];

// ===== FPS role: round-10 core + binary-descent winner index (exact lowest-index) ============
__device__ void fps_body(const float* __restrict__ p, int b) {
    const int tid = threadIdx.x;
    const float* pb = p + (size_t)b*Nz*3;
    float* spx = fused_sm; float* spy = fused_sm + Nz; float* spz = fused_sm + 2*Nz;
    __shared__ unsigned s_bv[8];
    __shared__ unsigned s_wi[2];

    for (int i = tid; i < Nz; i += 256) {
        spx[i] = pb[3*i+0]; spy[i] = pb[3*i+1]; spz[i] = pb[3*i+2];
    }
    if (tid == 0) { s_wi[0] = 0xFFFFFFFFu; s_wi[1] = 0xFFFFFFFFu; }
    __syncthreads();

    ull px2[16], py2[16], pz2[16];
    float dd[32];
#pragma unroll
    for (int u = 0; u < 16; ++u) {
        int i0 = tid + (2*u)*256, i1 = i0 + 256;
        px2[u] = PK(spx[i0], spx[i1]);
        py2[u] = PK(spy[i0], spy[i1]);
        pz2[u] = PK(spz[i0], spz[i1]);
        dd[2*u] = 1e10f; dd[2*u+1] = 1e10f;
    }
    float lx = spx[0], ly = spy[0], lz = spz[0];
    if (tid == 0) {
        float qq = __fadd_rn(__fadd_rn(__fmul_rn(lx,lx), __fmul_rn(ly,ly)), __fmul_rn(lz,lz));
        g_q[b*Mz] = make_float4(lx, ly, lz, qq);
    }

    for (int t = 1; t < Mz; ++t) {
        const ull nx2 = PK(-lx,-lx), ny2 = PK(-ly,-ly), nz2 = PK(-lz,-lz);
        float m16[16];
#pragma unroll
        for (int u = 0; u < 16; ++u) {
            ull dx2 = ADD2(px2[u], nx2);
            ull dy2 = ADD2(py2[u], ny2);
            ull dz2 = ADD2(pz2[u], nz2);
            ull d2  = MUL2(dx2, dx2);
            d2 = FMA2(dy2, dy2, d2);
            d2 = FMA2(dz2, dz2, d2);
            float d0, d1; UPK(d2, d0, d1);
            float n0 = fminf(dd[2*u],   d0);
            float n1 = fminf(dd[2*u+1], d1);
            dd[2*u] = n0; dd[2*u+1] = n1;
            m16[u] = fmaxf(n0, n1);
        }
        // contiguous pairwise max tree, levels kept live (same 15 fmax as before)
        float L8[8], L4a[4], L2a[2];
#pragma unroll
        for (int i = 0; i < 8; ++i) L8[i] = fmaxf(m16[2*i], m16[2*i+1]);
#pragma unroll
        for (int i = 0; i < 4; ++i) L4a[i] = fmaxf(L8[2*i], L8[2*i+1]);
        L2a[0] = fmaxf(L4a[0], L4a[1]); L2a[1] = fmaxf(L4a[2], L4a[3]);
        const float bv = fmaxf(L2a[0], L2a[1]);

        unsigned wmax = __reduce_max_sync(0xffffffffu, __float_as_uint(bv));
        if ((tid & 31) == 0) s_bv[tid >> 5] = wmax;
        __syncthreads();                               // bar 1
        unsigned gb = s_bv[0];
#pragma unroll
        for (int w = 1; w < 8; ++w) gb = umax(gb, s_bv[w]);
        const float bvg = __uint_as_float(gb);
        const int buf = t & 1;
        if (tid == 0) s_wi[buf^1] = 0xFFFFFFFFu;
        if (__float_as_uint(bv) == gb) {
            // exact binary descent, left-first => lowest dd-index with dd == bvg
            const float g = bvg;
            const bool s1 = (L2a[0] == g);                         // u3==0 ?
            const float c0 = s1 ? L4a[0] : L4a[2];
            const bool s2 = (c0 == g);                             // u2==0 ?
            const float d0a = s2 ? L8[0] : L8[2];                  // u3=0 branch
            const float d0b = s2 ? L8[4] : L8[6];                  // u3=1 branch
            const float d0  = s1 ? d0a : d0b;
            const bool s3 = (d0 == g);                             // u1==0 ?
            const float g00 = s3 ? m16[0]  : m16[2];
            const float g01 = s3 ? m16[4]  : m16[6];
            const float g10 = s3 ? m16[8]  : m16[10];
            const float g11 = s3 ? m16[12] : m16[14];
            const float h0 = s2 ? g00 : g01;
            const float h1 = s2 ? g10 : g11;
            const float e  = s1 ? h0 : h1;
            const bool s4 = (e == g);                              // u0==0 ?
            const int u = (s1?0:8) + (s2?0:4) + (s3?0:2) + (s4?0:1);
            // left element dd[2u] mux (15 selects)
            const float t000 = s4 ? dd[0]  : dd[2];
            const float t001 = s4 ? dd[4]  : dd[6];
            const float t010 = s4 ? dd[8]  : dd[10];
            const float t011 = s4 ? dd[12] : dd[14];
            const float t100 = s4 ? dd[16] : dd[18];
            const float t101 = s4 ? dd[20] : dd[22];
            const float t110 = s4 ? dd[24] : dd[26];
            const float t111 = s4 ? dd[28] : dd[30];
            const float r00 = s3 ? t000 : t001;
            const float r01 = s3 ? t010 : t011;
            const float r10 = s3 ? t100 : t101;
            const float r11 = s3 ? t110 : t111;
            const float v0 = s2 ? r00 : r01;
            const float v1 = s2 ? r10 : r11;
            const float dleft = s1 ? v0 : v1;
            const int elem = 2*u + ((dleft == g) ? 0 : 1);
            atomicMin(&s_wi[buf], (unsigned)(tid + elem*256));     // lowest global index wins
        }
        __syncthreads();                               // bar 2
        const unsigned wi = s_wi[buf];
        lx = spx[wi]; ly = spy[wi]; lz = spz[wi];
        if (tid == 0) {
            float qq = __fadd_rn(__fadd_rn(__fmul_rn(lx,lx), __fmul_rn(ly,ly)), __fmul_rn(lz,lz));
            g_q[b*Mz + t] = make_float4(lx, ly, lz, qq);
            if ((t & 63) == 63) {
                __threadfence();
                g_prog[b] = (unsigned)(t + 1);
            }
        }
    }
}

// ===== kNN slice unit: waits on FPS progress (producer resident: single wave) ================
__device__ void knn_unit(const float* __restrict__ p, int e) {
    ull (*spt)[4] = (ull(*)[4])fused_sm;    // 16kB tile
    const int tid = threadIdx.x;
    const int qb = e & 31, sl = e >> 5;
    const int b  = qb >> 3;
    const float* pb = p + (size_t)b*Nz*3;
    const int t0 = sl * SLEN;

    for (int i = tid; i < SLEN/2; i += 256) {
        int i0 = t0 + 2*i, i1 = i0 + 1;
        float x0 = pb[3*i0+0], y0 = pb[3*i0+1], z0 = pb[3*i0+2];
        float x1 = pb[3*i1+0], y1 = pb[3*i1+1], z1 = pb[3*i1+2];
        float w0 = __fadd_rn(__fadd_rn(__fmul_rn(x0,x0), __fmul_rn(y0,y0)), __fmul_rn(z0,z0));
        float w1 = __fadd_rn(__fadd_rn(__fmul_rn(x1,x1), __fmul_rn(y1,y1)), __fmul_rn(z1,z1));
        spt[i][0] = PK(x0,x1); spt[i][1] = PK(y0,y1);
        spt[i][2] = PK(z0,z1); spt[i][3] = PK(w0,w1);
    }
    if (tid == 0) {
        const unsigned need = ((unsigned)(qb & 7) + 1u) * 256u;
        while (g_prog[b] < need) __nanosleep(256);
        __threadfence();
    }
    __syncthreads();

    const int qi = qb*256 + tid;
    const float4 q = g_q[qi];
    const ull qx2 = PK(q.x,q.x), qy2 = PK(q.y,q.y), qz2 = PK(q.z,q.z);
    const ull qw2 = PK(q.w,q.w), n2 = PK(-2.0f,-2.0f);

    float nd[Kz]; int ni[Kz];
#pragma unroll
    for (int j = 0; j < Kz; ++j) { nd[j] = 1e30f; ni[j] = 0; }
    float wk = 1e30f;

    for (int u = 0; u < SLEN/2; ++u) {
        const ulonglong2* r = (const ulonglong2*)spt[u];
        ulonglong2 r0 = r[0], r1 = r[1];
        ull a2 = MUL2(qx2, r0.x);
        a2 = FMA2(qy2, r0.y, a2);
        a2 = FMA2(qz2, r1.x, a2);
        ull a3 = ADD2(qw2, r1.y);
        ull d2 = FMA2(a2, n2, a3);
        float d0, d1; UPK(d2, d0, d1);
        if (d0 < wk) {
            float cd = d0; int ci = t0 + 2*u;
#pragma unroll
            for (int j = 0; j < Kz; ++j)
                if (cd < nd[j]) { float td = nd[j]; int ti = ni[j]; nd[j] = cd; ni[j] = ci; cd = td; ci = ti; }
            wk = nd[Kz-1];
        }
        if (d1 < wk) {
            float cd = d1; int ci = t0 + 2*u + 1;
#pragma unroll
            for (int j = 0; j < Kz; ++j)
                if (cd < nd[j]) { float td = nd[j]; int ti = ni[j]; nd[j] = cd; ni[j] = ci; cd = td; ci = ti; }
            wk = nd[Kz-1];
        }
    }
    const size_t base = ((size_t)qi*NSLICE + sl)*Kz;
#pragma unroll
    for (int j = 0; j < Kz; ++j) { g_kd[base+j] = nd[j]; g_ki[base+j] = ni[j]; }
}

// ===== fused kernel: 148 blocks = one wave; FPS || kNN ======================================
__global__ void __launch_bounds__(256,1) fused_kernel(const float* __restrict__ p) {
    if (blockIdx.x < Bz) {
        fps_body(p, blockIdx.x);
        return;
    }
    const int w = blockIdx.x - Bz;           // 0..143
    knn_unit(p, w);
    if (w + NWORK < 256) {
        __syncthreads();                     // protect smem tile reuse
        knn_unit(p, w + NWORK);
    }
}

// ---- exact 8-way merge of per-slice sorted (d, idx) lists -> global top-20 ----
__global__ void __launch_bounds__(64) kmerge_kernel() {
    const int qi = blockIdx.x*64 + threadIdx.x;
    float dc[NSLICE]; int ic[NSLICE]; int h[NSLICE];
#pragma unroll
    for (int s = 0; s < NSLICE; ++s) {
        size_t base = ((size_t)qi*NSLICE + s)*Kz;
        dc[s] = g_kd[base]; ic[s] = g_ki[base]; h[s] = 0;
    }
    for (int j = 0; j < Kz; ++j) {
        int bs = 0;
#pragma unroll
        for (int s = 1; s < NSLICE; ++s)
            if (dc[s] < dc[bs] || (dc[s] == dc[bs] && ic[s] < ic[bs])) bs = s;
        g_nidx[(size_t)qi*Kz + j] = ic[bs];
        h[bs]++;
        if (h[bs] < Kz) {
            size_t off = ((size_t)qi*NSLICE + bs)*Kz + h[bs];
            dc[bs] = g_kd[off]; ic[bs] = g_ki[off];
        } else { dc[bs] = 3.0e38f; ic[bs] = 0x7FFFFFFF; }
    }
}

// ====== conv1: 1 thread = 1 group-point, [6->64] matvec + leaky + fused BN stats ======
__global__ void __launch_bounds__(128) conv1_kernel(const float* __restrict__ p,
                                                    const float* __restrict__ W1) {
    __shared__ __align__(16) float sWc[64][8];
    __shared__ __align__(16) float so[128*68];
    __shared__ float sps[2][64], sqs[2][64];
    const int tid = threadIdx.x;
    if (tid < 64) {
#pragma unroll
        for (int j = 0; j < 6; ++j) sWc[tid][j] = W1[tid*6 + j];
        sWc[tid][6] = 0.f; sWc[tid][7] = 0.f;
    }
    const int gp0 = blockIdx.x * 128;
    const int gp = gp0 + tid;
    const int m = (gp / Kz) % Mz;
    const int b = gp / (Kz*Mz);
    const int nid = g_nidx[gp];
    const float* pr = p + ((size_t)b*Nz + nid)*3;
    float gx = pr[0], gy = pr[1], gz = pr[2];
    float4 q = g_q[b*Mz + m];
    float f0 = __fsub_rn(gx, q.x), f1 = __fsub_rn(gy, q.y), f2 = __fsub_rn(gz, q.z);
    __syncthreads();
#pragma unroll 4
    for (int c = 0; c < 64; ++c) {
        float4 w0 = *(const float4*)&sWc[c][0];
        float2 w1 = *(const float2*)&sWc[c][4];
        float acc = w0.x * f0;
        acc = fmaf(w0.y, f1, acc);
        acc = fmaf(w0.z, f2, acc);
        acc = fmaf(w0.w, gx, acc);
        acc = fmaf(w1.x, gy, acc);
        acc = fmaf(w1.y, gz, acc);
        so[tid*68 + c] = (acc >= 0.f) ? acc : 0.2f*acc;
    }
    __syncthreads();
    {
        int c = tid & 63, h = tid >> 6;
        float s = 0.f, s2 = 0.f;
#pragma unroll 8
        for (int r = h*64; r < h*64 + 64; ++r) {
            float v = so[r*68 + c];
            s += v; s2 = fmaf(v, v, s2);
        }
        sps[h][c] = s; sqs[h][c] = s2;
    }
    __syncthreads();
    if (tid < 64) {
        atomicAdd(&g_sum[tid],      (double)(sps[0][tid] + sps[1][tid]));
        atomicAdd(&g_sum[64 + tid], (double)(sqs[0][tid] + sqs[1][tid]));
    }
    for (int idx = tid; idx < 2048; idx += 128) {
        int row = idx >> 4, sg = idx & 15;
        float4 v = *(const float4*)&so[row*68 + sg*4];
        *(float4*)(g_x1 + (size_t)(gp0 + row)*64 + sg*4) = v;
    }
}

// ======== conv2/3: FFMA2 [64->64] matvec, 4 pts/thread, smem weights (round-10 form) ========
#define WJ 10
#define WCG (64*WJ + 4)
__global__ void __launch_bounds__(128) conv_kernel(int in_sel, const float* __restrict__ W,
                                                   int aff_stage) {
    const float* xin = in_sel ? g_x2 : g_x1;
    float*      xout = in_sel ? g_x1 : g_x2;
    __shared__ __align__(16) ull  sw[4*WCG];
    __shared__ __align__(16) float sx[128][65];
    __shared__ float sa[64], sc[64];
    __shared__ float ssumW[4*64], ssqW[4*64];
    const int tid = threadIdx.x;
    const int ww = tid >> 5, lane = tid & 31;

    for (int k = tid; k < 2048; k += 128) {
        int cgk = k >> 9, rem = k & 511, j = rem >> 3, qq = rem & 7;
        int c0 = cgk*16 + 2*qq;
        sw[cgk*WCG + j*WJ + qq] = PK(W[c0*64 + j], W[(c0+1)*64 + j]);
    }
    if (tid < 64) {
        sa[tid] = g_aff[aff_stage*128 + tid];
        sc[tid] = g_aff[aff_stage*128 + 64 + tid];
    }
    __syncthreads();
    const int p0 = blockIdx.x * 128;
    for (int idx = tid; idx < 8192; idx += 128) {
        int j = idx & 63;
        float v = xin[(size_t)p0*64 + idx];
        sx[idx >> 6][j] = fmaf(sa[j], v, sc[j]);
    }
    __syncthreads();

    const int ptb = tid >> 2, cg = tid & 3;
    const ull* wbase = &sw[cg*WCG];
    ull acc[4][8];
#pragma unroll
    for (int k = 0; k < 4; ++k)
#pragma unroll
        for (int qq = 0; qq < 8; ++qq) acc[k][qq] = 0ull;

    for (int j = 0; j < 64; ++j) {
        const ulonglong2* wr = (const ulonglong2*)(wbase + j*WJ);
        ulonglong2 w01 = wr[0], w23 = wr[1], w45 = wr[2], w67 = wr[3];
        ull wv[8] = {w01.x, w01.y, w23.x, w23.y, w45.x, w45.y, w67.x, w67.y};
#pragma unroll
        for (int k = 0; k < 4; ++k) {
            float xv = sx[ptb + 32*k][j];
            ull xv2 = PK(xv, xv);
#pragma unroll
            for (int qq = 0; qq < 8; ++qq)
                acc[k][qq] = FMA2(wv[qq], xv2, acc[k][qq]);
        }
    }
    float sacc[16], sqacc[16];
#pragma unroll
    for (int i = 0; i < 16; ++i) { sacc[i] = 0.f; sqacc[i] = 0.f; }
#pragma unroll
    for (int k = 0; k < 4; ++k) {
        float o[16];
#pragma unroll
        for (int qq = 0; qq < 8; ++qq) {
            float lo, hi; UPK(acc[k][qq], lo, hi);
            o[2*qq]   = (lo >= 0.f) ? lo : 0.2f*lo;
            o[2*qq+1] = (hi >= 0.f) ? hi : 0.2f*hi;
        }
#pragma unroll
        for (int i = 0; i < 16; ++i) {
            sacc[i] += o[i];
            sqacc[i] = fmaf(o[i], o[i], sqacc[i]);
        }
        float4* op = (float4*)(xout + (size_t)(p0 + ptb + 32*k)*64 + cg*16);
#pragma unroll
        for (int v4 = 0; v4 < 4; ++v4)
            op[v4] = make_float4(o[4*v4], o[4*v4+1], o[4*v4+2], o[4*v4+3]);
    }
#pragma unroll
    for (int o = 4; o <= 16; o <<= 1) {
#pragma unroll
        for (int i = 0; i < 16; ++i) {
            sacc[i]  += __shfl_xor_sync(0xffffffffu, sacc[i],  o);
            sqacc[i] += __shfl_xor_sync(0xffffffffu, sqacc[i], o);
        }
    }
    if (lane < 4) {
#pragma unroll
        for (int i = 0; i < 16; ++i) {
            ssumW[ww*64 + lane*16 + i] = sacc[i];
            ssqW [ww*64 + lane*16 + i] = sqacc[i];
        }
    }
    __syncthreads();
    if (tid < 64) {
        float S = 0.f, Q = 0.f;
#pragma unroll
        for (int v = 0; v < 4; ++v) { S += ssumW[v*64 + tid]; Q += ssqW[v*64 + tid]; }
        atomicAdd(&g_sum[tid],      (double)S);
        atomicAdd(&g_sum[64 + tid], (double)Q);
    }
}

// ---------------- BN finalize: affine a,c; re-zeroes accumulators ----------------
__global__ void bnfin_kernel(int stage, const float* __restrict__ g, const float* __restrict__ bb) {
    const int c = threadIdx.x;   // 64 threads
    const double cnt = (double)PTS;
    double mean = g_sum[c] / cnt;
    double var  = g_sum[64 + c] / cnt - mean*mean;
    double inv  = 1.0 / sqrt(var + 1e-5);
    float a  = (float)((double)g[c] * inv);
    float cc = (float)((double)bb[c] - (double)a * mean);
    g_aff[stage*128 + c]      = a;
    g_aff[stage*128 + 64 + c] = cc;
    g_sum[c] = 0.0; g_sum[64 + c] = 0.0;
}

// ---------------- final: apply BN3 affine, max over K ----------------
__global__ void __launch_bounds__(256) maxk_kernel(float* __restrict__ out) {
    const int t = blockIdx.x*256 + threadIdx.x;
    const int c = t & 63;
    const int m = (t >> 6) & 2047;
    const int b = t >> 17;
    const float* base = g_x1 + ((size_t)(b*Mz + m)*Kz)*64 + c;
    const float a  = g_aff[2*128 + c];
    const float cc = g_aff[2*128 + 64 + c];
    float mx = -1e30f;
#pragma unroll
    for (int k = 0; k < Kz; ++k) {
        float v = fmaf(a, base[(size_t)k*64], cc);
        mx = fmaxf(mx, v);
    }
    out[((size_t)(b*64 + c))*Mz + m] = mx;
}

// ---------------- launch (round-10 sequence) ----------------
extern "C" void kernel_launch(void* const* d_in, const int* in_sizes, int n_in,
                              void* d_out, int out_size) {
    (void)in_sizes; (void)n_in; (void)out_size;
    const float* p  = (const float*)d_in[0];
    const float* W1 = (const float*)d_in[1];
    const float* g1 = (const float*)d_in[2];
    const float* b1 = (const float*)d_in[3];
    const float* W2 = (const float*)d_in[4];
    const float* g2 = (const float*)d_in[5];
    const float* b2 = (const float*)d_in[6];
    const float* W3 = (const float*)d_in[7];
    const float* g3 = (const float*)d_in[8];
    const float* b3 = (const float*)d_in[9];
    float* out = (float*)d_out;

    cudaFuncSetAttribute(fused_kernel, cudaFuncAttributeMaxDynamicSharedMemorySize, FUSED_SMEM);

    fused_kernel<<<Bz + NWORK, 256, FUSED_SMEM>>>(p);
    kmerge_kernel<<<(Bz*Mz)/64, 64>>>();
    conv1_kernel<<<PTS/128, 128>>>(p, W1);
    bnfin_kernel<<<1, 64>>>(0, g1, b1);
    conv_kernel<<<PTS/128, 128>>>(0, W2, 0);
    bnfin_kernel<<<1, 64>>>(1, g2, b2);
    conv_kernel<<<PTS/128, 128>>>(1, W3, 1);
    bnfin_kernel<<<1, 64>>>(2, g3, b3);
    maxk_kernel<<<(Bz*Mz*Cz)/256, 256>>>(out);
}

// round 17
// speedup vs baseline: 1.1954x; 1.0405x over previous
#include <cuda_runtime.h>

#define Bz 4
#define Nz 8192
#define Mz 2048
#define Kz 20
#define Cz 64
#define PTS (Bz*Mz*Kz)   // 163840
#define NSLICE 8
#define SLEN 1024
#define NWORK 144
#define FUSED_SMEM (3*Nz*4)   // 96kB dynamic

typedef unsigned long long ull;

// ---------------- packed f32x2 helpers (sm_100+: add/mul/fma only) ----------------
__device__ __forceinline__ ull PK(float lo, float hi) {
    ull r; asm("mov.b64 %0, {%1,%2};" : "=l"(r) : "f"(lo), "f"(hi)); return r;
}
__device__ __forceinline__ void UPK(ull v, float& lo, float& hi) {
    asm("mov.b64 {%0,%1}, %2;" : "=f"(lo), "=f"(hi) : "l"(v));
}
__device__ __forceinline__ ull ADD2(ull a, ull b) {
    ull r; asm("add.rn.f32x2 %0, %1, %2;" : "=l"(r) : "l"(a), "l"(b)); return r;
}
__device__ __forceinline__ ull MUL2(ull a, ull b) {
    ull r; asm("mul.rn.f32x2 %0, %1, %2;" : "=l"(r) : "l"(a), "l"(b)); return r;
}
__device__ __forceinline__ ull FMA2(ull a, ull b, ull c) {
    ull r; asm("fma.rn.f32x2 %0, %1, %2, %3;" : "=l"(r) : "l"(a), "l"(b), "l"(c)); return r;
}

// ---------------- scratch (static device globals; no allocation) ----------------
__device__ float4 g_q[Bz*Mz];                    // sampled pts: x,y,z,|q|^2
__device__ int    g_nidx[Bz*Mz*Kz];              // final knn indices
__device__ float  g_kd[Bz*Mz*NSLICE*Kz];         // per-slice partial top-20 dists
__device__ int    g_ki[Bz*Mz*NSLICE*Kz];         // per-slice partial top-20 idx
__device__ float  g_x1[(size_t)PTS*Cz];          // ~42MB
__device__ float  g_x2[(size_t)PTS*Cz];          // ~42MB
__device__ double g_sum[2*Cz];                   // per-channel sum/sumsq (re-zeroed by bnfin)
__device__ float  g_aff[3*2*Cz];                 // per-stage BN affine: a[64], c[64]
__device__ volatile unsigned g_prog[Bz];         // FPS progress per batch (handshake)

extern __shared__ float fused_sm[];

// ===== FPS: round-16 core; block max via shared atomicMax (single-LDS combine) ===============
__device__ void fps_body(const float* __restrict__ p, int b) {
    const int tid = threadIdx.x;
    const float* pb = p + (size_t)b*Nz*3;
    float* spx = fused_sm; float* spy = fused_sm + Nz; float* spz = fused_sm + 2*Nz;
    __shared__ unsigned s_gb[2];
    __shared__ unsigned s_wi[2];

    for (int i = tid; i < Nz; i += 256) {
        spx[i] = pb[3*i+0]; spy[i] = pb[3*i+1]; spz[i] = pb[3*i+2];
    }
    if (tid == 0) {
        s_wi[0] = 0xFFFFFFFFu; s_wi[1] = 0xFFFFFFFFu;
        s_gb[0] = 0u; s_gb[1] = 0u;
    }
    __syncthreads();

    ull px2[16], py2[16], pz2[16];
    float dd[32];
#pragma unroll
    for (int u = 0; u < 16; ++u) {
        int i0 = tid + (2*u)*256, i1 = i0 + 256;
        px2[u] = PK(spx[i0], spx[i1]);
        py2[u] = PK(spy[i0], spy[i1]);
        pz2[u] = PK(spz[i0], spz[i1]);
        dd[2*u] = 1e10f; dd[2*u+1] = 1e10f;
    }
    float lx = spx[0], ly = spy[0], lz = spz[0];
    if (tid == 0) {
        float qq = __fadd_rn(__fadd_rn(__fmul_rn(lx,lx), __fmul_rn(ly,ly)), __fmul_rn(lz,lz));
        g_q[b*Mz] = make_float4(lx, ly, lz, qq);
    }

    for (int t = 1; t < Mz; ++t) {
        const ull nx2 = PK(-lx,-lx), ny2 = PK(-ly,-ly), nz2 = PK(-lz,-lz);
        float m16[16];
#pragma unroll
        for (int u = 0; u < 16; ++u) {
            ull dx2 = ADD2(px2[u], nx2);
            ull dy2 = ADD2(py2[u], ny2);
            ull dz2 = ADD2(pz2[u], nz2);
            ull d2  = MUL2(dx2, dx2);
            d2 = FMA2(dy2, dy2, d2);
            d2 = FMA2(dz2, dz2, d2);
            float d0, d1; UPK(d2, d0, d1);
            float n0 = fminf(dd[2*u],   d0);
            float n1 = fminf(dd[2*u+1], d1);
            dd[2*u] = n0; dd[2*u+1] = n1;
            m16[u] = fmaxf(n0, n1);
        }
        // contiguous pairwise max tree, levels kept live
        float L8[8], L4a[4], L2a[2];
#pragma unroll
        for (int i = 0; i < 8; ++i) L8[i] = fmaxf(m16[2*i], m16[2*i+1]);
#pragma unroll
        for (int i = 0; i < 4; ++i) L4a[i] = fmaxf(L8[2*i], L8[2*i+1]);
        L2a[0] = fmaxf(L4a[0], L4a[1]); L2a[1] = fmaxf(L4a[2], L4a[3]);
        const float bv = fmaxf(L2a[0], L2a[1]);

        const int buf = t & 1;
        unsigned wmax = __reduce_max_sync(0xffffffffu, __float_as_uint(bv));
        if ((tid & 31) == 0) atomicMax(&s_gb[buf], wmax);      // 8 atomics, one per warp
        __syncthreads();                               // bar 1
        const unsigned gb = s_gb[buf];
        const float bvg = __uint_as_float(gb);
        if (tid == 0) { s_wi[buf^1] = 0xFFFFFFFFu; s_gb[buf^1] = 0u; }   // reset next-step bufs
        if (__float_as_uint(bv) == gb) {
            // exact binary descent, left-first => lowest dd-index with dd == bvg
            const float g = bvg;
            const bool s1 = (L2a[0] == g);
            const float c0 = s1 ? L4a[0] : L4a[2];
            const bool s2 = (c0 == g);
            const float d0a = s2 ? L8[0] : L8[2];
            const float d0b = s2 ? L8[4] : L8[6];
            const float d0  = s1 ? d0a : d0b;
            const bool s3 = (d0 == g);
            const float g00 = s3 ? m16[0]  : m16[2];
            const float g01 = s3 ? m16[4]  : m16[6];
            const float g10 = s3 ? m16[8]  : m16[10];
            const float g11 = s3 ? m16[12] : m16[14];
            const float h0 = s2 ? g00 : g01;
            const float h1 = s2 ? g10 : g11;
            const float e  = s1 ? h0 : h1;
            const bool s4 = (e == g);
            const int u = (s1?0:8) + (s2?0:4) + (s3?0:2) + (s4?0:1);
            const float t000 = s4 ? dd[0]  : dd[2];
            const float t001 = s4 ? dd[4]  : dd[6];
            const float t010 = s4 ? dd[8]  : dd[10];
            const float t011 = s4 ? dd[12] : dd[14];
            const float t100 = s4 ? dd[16] : dd[18];
            const float t101 = s4 ? dd[20] : dd[22];
            const float t110 = s4 ? dd[24] : dd[26];
            const float t111 = s4 ? dd[28] : dd[30];
            const float r00 = s3 ? t000 : t001;
            const float r01 = s3 ? t010 : t011;
            const float r10 = s3 ? t100 : t101;
            const float r11 = s3 ? t110 : t111;
            const float v0 = s2 ? r00 : r01;
            const float v1 = s2 ? r10 : r11;
            const float dleft = s1 ? v0 : v1;
            const int elem = 2*u + ((dleft == g) ? 0 : 1);
            atomicMin(&s_wi[buf], (unsigned)(tid + elem*256));  // lowest global index wins
        }
        __syncthreads();                               // bar 2
        const unsigned wi = s_wi[buf];
        lx = spx[wi]; ly = spy[wi]; lz = spz[wi];
        if (tid == 0) {
            float qq = __fadd_rn(__fadd_rn(__fmul_rn(lx,lx), __fmul_rn(ly,ly)), __fmul_rn(lz,lz));
            g_q[b*Mz + t] = make_float4(lx, ly, lz, qq);
            if ((t & 63) == 63) {
                __threadfence();
                g_prog[b] = (unsigned)(t + 1);
            }
        }
    }
}

// ===== kNN slice unit: waits on FPS progress (producer resident: single wave) ================
__device__ void knn_unit(const float* __restrict__ p, int e) {
    ull (*spt)[4] = (ull(*)[4])fused_sm;    // 16kB tile
    const int tid = threadIdx.x;
    const int qb = e & 31, sl = e >> 5;
    const int b  = qb >> 3;
    const float* pb = p + (size_t)b*Nz*3;
    const int t0 = sl * SLEN;

    for (int i = tid; i < SLEN/2; i += 256) {
        int i0 = t0 + 2*i, i1 = i0 + 1;
        float x0 = pb[3*i0+0], y0 = pb[3*i0+1], z0 = pb[3*i0+2];
        float x1 = pb[3*i1+0], y1 = pb[3*i1+1], z1 = pb[3*i1+2];
        float w0 = __fadd_rn(__fadd_rn(__fmul_rn(x0,x0), __fmul_rn(y0,y0)), __fmul_rn(z0,z0));
        float w1 = __fadd_rn(__fadd_rn(__fmul_rn(x1,x1), __fmul_rn(y1,y1)), __fmul_rn(z1,z1));
        spt[i][0] = PK(x0,x1); spt[i][1] = PK(y0,y1);
        spt[i][2] = PK(z0,z1); spt[i][3] = PK(w0,w1);
    }
    if (tid == 0) {
        const unsigned need = ((unsigned)(qb & 7) + 1u) * 256u;
        while (g_prog[b] < need) __nanosleep(256);
        __threadfence();
    }
    __syncthreads();

    const int qi = qb*256 + tid;
    const float4 q = g_q[qi];
    const ull qx2 = PK(q.x,q.x), qy2 = PK(q.y,q.y), qz2 = PK(q.z,q.z);
    const ull qw2 = PK(q.w,q.w), n2 = PK(-2.0f,-2.0f);

    float nd[Kz]; int ni[Kz];
#pragma unroll
    for (int j = 0; j < Kz; ++j) { nd[j] = 1e30f; ni[j] = 0; }
    float wk = 1e30f;

    for (int u = 0; u < SLEN/2; ++u) {
        const ulonglong2* r = (const ulonglong2*)spt[u];
        ulonglong2 r0 = r[0], r1 = r[1];
        ull a2 = MUL2(qx2, r0.x);
        a2 = FMA2(qy2, r0.y, a2);
        a2 = FMA2(qz2, r1.x, a2);
        ull a3 = ADD2(qw2, r1.y);
        ull d2 = FMA2(a2, n2, a3);
        float d0, d1; UPK(d2, d0, d1);
        if (d0 < wk) {
            float cd = d0; int ci = t0 + 2*u;
#pragma unroll
            for (int j = 0; j < Kz; ++j)
                if (cd < nd[j]) { float td = nd[j]; int ti = ni[j]; nd[j] = cd; ni[j] = ci; cd = td; ci = ti; }
            wk = nd[Kz-1];
        }
        if (d1 < wk) {
            float cd = d1; int ci = t0 + 2*u + 1;
#pragma unroll
            for (int j = 0; j < Kz; ++j)
                if (cd < nd[j]) { float td = nd[j]; int ti = ni[j]; nd[j] = cd; ni[j] = ci; cd = td; ci = ti; }
            wk = nd[Kz-1];
        }
    }
    const size_t base = ((size_t)qi*NSLICE + sl)*Kz;
#pragma unroll
    for (int j = 0; j < Kz; ++j) { g_kd[base+j] = nd[j]; g_ki[base+j] = ni[j]; }
}

// ===== fused kernel: 148 blocks = one wave; FPS || kNN =======================================
// unit remap: the 32 late units (e % 8 == 7, need FPS completion) go one-each to
// single-unit blocks 112..143; the 224 early units (need <= 1792, hidden) pair on blocks 0..111.
__global__ void __launch_bounds__(256,1) fused_kernel(const float* __restrict__ p) {
    if (blockIdx.x < Bz) {
        fps_body(p, blockIdx.x);
        return;
    }
    const int w = blockIdx.x - Bz;           // 0..143
    if (w < 112) {
        const int iA = w, iB = w + 112;      // early-unit indices (0..223)
        const int eA = (iA/7)*8 + (iA%7);
        const int eB = (iB/7)*8 + (iB%7);
        knn_unit(p, eA);
        __syncthreads();                     // protect smem tile reuse
        knn_unit(p, eB);
    } else {
        knn_unit(p, (w - 112)*8 + 7);        // late unit (unlocks at FPS end)
    }
}

// ---- exact 8-way merge of per-slice sorted (d, idx) lists -> global top-20 ----
__global__ void __launch_bounds__(64) kmerge_kernel() {
    const int qi = blockIdx.x*64 + threadIdx.x;
    float dc[NSLICE]; int ic[NSLICE]; int h[NSLICE];
#pragma unroll
    for (int s = 0; s < NSLICE; ++s) {
        size_t base = ((size_t)qi*NSLICE + s)*Kz;
        dc[s] = g_kd[base]; ic[s] = g_ki[base]; h[s] = 0;
    }
    for (int j = 0; j < Kz; ++j) {
        int bs = 0;
#pragma unroll
        for (int s = 1; s < NSLICE; ++s)
            if (dc[s] < dc[bs] || (dc[s] == dc[bs] && ic[s] < ic[bs])) bs = s;
        g_nidx[(size_t)qi*Kz + j] = ic[bs];
        h[bs]++;
        if (h[bs] < Kz) {
            size_t off = ((size_t)qi*NSLICE + bs)*Kz + h[bs];
            dc[bs] = g_kd[off]; ic[bs] = g_ki[off];
        } else { dc[bs] = 3.0e38f; ic[bs] = 0x7FFFFFFF; }
    }
}

// ====== conv1: 1 thread = 1 group-point, [6->64] matvec + leaky + fused BN stats ======
__global__ void __launch_bounds__(128) conv1_kernel(const float* __restrict__ p,
                                                    const float* __restrict__ W1) {
    __shared__ __align__(16) float sWc[64][8];
    __shared__ __align__(16) float so[128*68];
    __shared__ float sps[2][64], sqs[2][64];
    const int tid = threadIdx.x;
    if (tid < 64) {
#pragma unroll
        for (int j = 0; j < 6; ++j) sWc[tid][j] = W1[tid*6 + j];
        sWc[tid][6] = 0.f; sWc[tid][7] = 0.f;
    }
    const int gp0 = blockIdx.x * 128;
    const int gp = gp0 + tid;
    const int m = (gp / Kz) % Mz;
    const int b = gp / (Kz*Mz);
    const int nid = g_nidx[gp];
    const float* pr = p + ((size_t)b*Nz + nid)*3;
    float gx = pr[0], gy = pr[1], gz = pr[2];
    float4 q = g_q[b*Mz + m];
    float f0 = __fsub_rn(gx, q.x), f1 = __fsub_rn(gy, q.y), f2 = __fsub_rn(gz, q.z);
    __syncthreads();
#pragma unroll 4
    for (int c = 0; c < 64; ++c) {
        float4 w0 = *(const float4*)&sWc[c][0];
        float2 w1 = *(const float2*)&sWc[c][4];
        float acc = w0.x * f0;
        acc = fmaf(w0.y, f1, acc);
        acc = fmaf(w0.z, f2, acc);
        acc = fmaf(w0.w, gx, acc);
        acc = fmaf(w1.x, gy, acc);
        acc = fmaf(w1.y, gz, acc);
        so[tid*68 + c] = (acc >= 0.f) ? acc : 0.2f*acc;
    }
    __syncthreads();
    {
        int c = tid & 63, h = tid >> 6;
        float s = 0.f, s2 = 0.f;
#pragma unroll 8
        for (int r = h*64; r < h*64 + 64; ++r) {
            float v = so[r*68 + c];
            s += v; s2 = fmaf(v, v, s2);
        }
        sps[h][c] = s; sqs[h][c] = s2;
    }
    __syncthreads();
    if (tid < 64) {
        atomicAdd(&g_sum[tid],      (double)(sps[0][tid] + sps[1][tid]));
        atomicAdd(&g_sum[64 + tid], (double)(sqs[0][tid] + sqs[1][tid]));
    }
    for (int idx = tid; idx < 2048; idx += 128) {
        int row = idx >> 4, sg = idx & 15;
        float4 v = *(const float4*)&so[row*68 + sg*4];
        *(float4*)(g_x1 + (size_t)(gp0 + row)*64 + sg*4) = v;
    }
}

// ======== conv2/3: FFMA2 [64->64] matvec, 4 pts/thread, smem weights (round-10 form) ========
#define WJ 10
#define WCG (64*WJ + 4)
__global__ void __launch_bounds__(128) conv_kernel(int in_sel, const float* __restrict__ W,
                                                   int aff_stage) {
    const float* xin = in_sel ? g_x2 : g_x1;
    float*      xout = in_sel ? g_x1 : g_x2;
    __shared__ __align__(16) ull  sw[4*WCG];
    __shared__ __align__(16) float sx[128][65];
    __shared__ float sa[64], sc[64];
    __shared__ float ssumW[4*64], ssqW[4*64];
    const int tid = threadIdx.x;
    const int ww = tid >> 5, lane = tid & 31;

    for (int k = tid; k < 2048; k += 128) {
        int cgk = k >> 9, rem = k & 511, j = rem >> 3, qq = rem & 7;
        int c0 = cgk*16 + 2*qq;
        sw[cgk*WCG + j*WJ + qq] = PK(W[c0*64 + j], W[(c0+1)*64 + j]);
    }
    if (tid < 64) {
        sa[tid] = g_aff[aff_stage*128 + tid];
        sc[tid] = g_aff[aff_stage*128 + 64 + tid];
    }
    __syncthreads();
    const int p0 = blockIdx.x * 128;
    for (int idx = tid; idx < 8192; idx += 128) {
        int j = idx & 63;
        float v = xin[(size_t)p0*64 + idx];
        sx[idx >> 6][j] = fmaf(sa[j], v, sc[j]);
    }
    __syncthreads();

    const int ptb = tid >> 2, cg = tid & 3;
    const ull* wbase = &sw[cg*WCG];
    ull acc[4][8];
#pragma unroll
    for (int k = 0; k < 4; ++k)
#pragma unroll
        for (int qq = 0; qq < 8; ++qq) acc[k][qq] = 0ull;

    for (int j = 0; j < 64; ++j) {
        const ulonglong2* wr = (const ulonglong2*)(wbase + j*WJ);
        ulonglong2 w01 = wr[0], w23 = wr[1], w45 = wr[2], w67 = wr[3];
        ull wv[8] = {w01.x, w01.y, w23.x, w23.y, w45.x, w45.y, w67.x, w67.y};
#pragma unroll
        for (int k = 0; k < 4; ++k) {
            float xv = sx[ptb + 32*k][j];
            ull xv2 = PK(xv, xv);
#pragma unroll
            for (int qq = 0; qq < 8; ++qq)
                acc[k][qq] = FMA2(wv[qq], xv2, acc[k][qq]);
        }
    }
    float sacc[16], sqacc[16];
#pragma unroll
    for (int i = 0; i < 16; ++i) { sacc[i] = 0.f; sqacc[i] = 0.f; }
#pragma unroll
    for (int k = 0; k < 4; ++k) {
        float o[16];
#pragma unroll
        for (int qq = 0; qq < 8; ++qq) {
            float lo, hi; UPK(acc[k][qq], lo, hi);
            o[2*qq]   = (lo >= 0.f) ? lo : 0.2f*lo;
            o[2*qq+1] = (hi >= 0.f) ? hi : 0.2f*hi;
        }
#pragma unroll
        for (int i = 0; i < 16; ++i) {
            sacc[i] += o[i];
            sqacc[i] = fmaf(o[i], o[i], sqacc[i]);
        }
        float4* op = (float4*)(xout + (size_t)(p0 + ptb + 32*k)*64 + cg*16);
#pragma unroll
        for (int v4 = 0; v4 < 4; ++v4)
            op[v4] = make_float4(o[4*v4], o[4*v4+1], o[4*v4+2], o[4*v4+3]);
    }
#pragma unroll
    for (int o = 4; o <= 16; o <<= 1) {
#pragma unroll
        for (int i = 0; i < 16; ++i) {
            sacc[i]  += __shfl_xor_sync(0xffffffffu, sacc[i],  o);
            sqacc[i] += __shfl_xor_sync(0xffffffffu, sqacc[i], o);
        }
    }
    if (lane < 4) {
#pragma unroll
        for (int i = 0; i < 16; ++i) {
            ssumW[ww*64 + lane*16 + i] = sacc[i];
            ssqW [ww*64 + lane*16 + i] = sqacc[i];
        }
    }
    __syncthreads();
    if (tid < 64) {
        float S = 0.f, Q = 0.f;
#pragma unroll
        for (int v = 0; v < 4; ++v) { S += ssumW[v*64 + tid]; Q += ssqW[v*64 + tid]; }
        atomicAdd(&g_sum[tid],      (double)S);
        atomicAdd(&g_sum[64 + tid], (double)Q);
    }
}

// ---------------- BN finalize: affine a,c; re-zeroes accumulators ----------------
__global__ void bnfin_kernel(int stage, const float* __restrict__ g, const float* __restrict__ bb) {
    const int c = threadIdx.x;   // 64 threads
    const double cnt = (double)PTS;
    double mean = g_sum[c] / cnt;
    double var  = g_sum[64 + c] / cnt - mean*mean;
    double inv  = 1.0 / sqrt(var + 1e-5);
    float a  = (float)((double)g[c] * inv);
    float cc = (float)((double)bb[c] - (double)a * mean);
    g_aff[stage*128 + c]      = a;
    g_aff[stage*128 + 64 + c] = cc;
    g_sum[c] = 0.0; g_sum[64 + c] = 0.0;
}

// ---------------- final: apply BN3 affine, max over K ----------------
__global__ void __launch_bounds__(256) maxk_kernel(float* __restrict__ out) {
    const int t = blockIdx.x*256 + threadIdx.x;
    const int c = t & 63;
    const int m = (t >> 6) & 2047;
    const int b = t >> 17;
    const float* base = g_x1 + ((size_t)(b*Mz + m)*Kz)*64 + c;
    const float a  = g_aff[2*128 + c];
    const float cc = g_aff[2*128 + 64 + c];
    float mx = -1e30f;
#pragma unroll
    for (int k = 0; k < Kz; ++k) {
        float v = fmaf(a, base[(size_t)k*64], cc);
        mx = fmaxf(mx, v);
    }
    out[((size_t)(b*64 + c))*Mz + m] = mx;
}

// ---------------- launch ----------------
extern "C" void kernel_launch(void* const* d_in, const int* in_sizes, int n_in,
                              void* d_out, int out_size) {
    (void)in_sizes; (void)n_in; (void)out_size;
    const float* p  = (const float*)d_in[0];
    const float* W1 = (const float*)d_in[1];
    const float* g1 = (const float*)d_in[2];
    const float* b1 = (const float*)d_in[3];
    const float* W2 = (const float*)d_in[4];
    const float* g2 = (const float*)d_in[5];
    const float* b2 = (const float*)d_in[6];
    const float* W3 = (const float*)d_in[7];
    const float* g3 = (const float*)d_in[8];
    const float* b3 = (const float*)d_in[9];
    float* out = (float*)d_out;

    cudaFuncSetAttribute(fused_kernel, cudaFuncAttributeMaxDynamicSharedMemorySize, FUSED_SMEM);

    fused_kernel<<<Bz + NWORK, 256, FUSED_SMEM>>>(p);
    kmerge_kernel<<<(Bz*Mz)/64, 64>>>();
    conv1_kernel<<<PTS/128, 128>>>(p, W1);
    bnfin_kernel<<<1, 64>>>(0, g1, b1);
    conv_kernel<<<PTS/128, 128>>>(0, W2, 0);
    bnfin_kernel<<<1, 64>>>(1, g2, b2);
    conv_kernel<<<PTS/128, 128>>>(1, W3, 1);
    bnfin_kernel<<<1, 64>>>(2, g3, b3);
    maxk_kernel<<<(Bz*Mz*Cz)/256, 256>>>(out);
}